// round 15
// baseline (speedup 1.0000x reference)
#include <cuda_runtime.h>
#include <cstdint>

#define T_LEN  16384
#define BATCH  10
#define DDIM   3
#define HDIM   4
#define NITER  10
#define NCHAIN (NITER*BATCH)   // 100
#define NGATE  16

// ---------------- device scratch (static: no allocation allowed) ----------------
// layout (u-major, gate-fastest): k = u*4 + gate, gates 0=i 1=f 2=o 3=g
__device__ float g_W2[NITER*DDIM*NGATE];                // [it][d][u][gate], exp-scale folded
__device__ float g_U2[NITER*HDIM*NGATE];                // [it][j][u][gate], exp-scale folded
__device__ float g_xproj[(size_t)NCHAIN*T_LEN*NGATE];   // 104.9 MB  [chain][t][u][gate]
__device__ float g_scratch[(size_t)T_LEN*NCHAIN*16];    // 104.9 MB  [t][chain][u][4] = (o,h,c,tc)

// ---------------- helpers: guaranteed single-MUFU ops ----------------
__device__ __forceinline__ float ex2_ap(float x) {
    float y; asm("ex2.approx.f32 %0, %1;" : "=f"(y) : "f"(x)); return y;
}
__device__ __forceinline__ float rcp_ap(float x) {
    float y; asm("rcp.approx.f32 %0, %1;" : "=f"(y) : "f"(x)); return y;
}

#define SCL_SIG  (-1.4426950408889634f)   // -log2(e):   sigmoid(x) = rcp(1 + 2^(x*SCL_SIG))
#define SCL_TANH (-2.8853900817779268f)   // -2*log2(e): tanh(x)    = 2*rcp(1 + 2^(x*SCL_TANH)) - 1

// ---------------- 1) fold masks & exp-scales into W2, U2 ----------------
// i,f,o gates carry -log2e (sigmoid form), g gate carries -2log2e (tanh form).
__global__ void setup_k(const float* __restrict__ zx, const float* __restrict__ zh,
                        const float* __restrict__ Wi, const float* __restrict__ Ui,
                        const float* __restrict__ Wf, const float* __restrict__ Uf,
                        const float* __restrict__ Wo, const float* __restrict__ Uo,
                        const float* __restrict__ Wg, const float* __restrict__ Ug) {
    int tid = blockIdx.x * blockDim.x + threadIdx.x;
    if (tid < NITER*DDIM*NGATE) {                  // W2[it][d][u][gate]
        int k = tid % NGATE, d = (tid / NGATE) % DDIM, it = tid / (NGATE*DDIM);
        int gate = k & 3, u = k >> 2;
        const float* W = (gate == 0) ? Wi : (gate == 1) ? Wf : (gate == 2) ? Wo : Wg;
        float s = (gate < 3) ? SCL_SIG : SCL_TANH;
        g_W2[tid] = zx[it*DDIM + d] * W[d*HDIM + u] * s;
    }
    if (tid < NITER*HDIM*NGATE) {                  // U2[it][j][u][gate]
        int k = tid % NGATE, j = (tid / NGATE) % HDIM, it = tid / (NGATE*HDIM);
        int gate = k & 3, u = k >> 2;
        const float* U = (gate == 0) ? Ui : (gate == 1) ? Uf : (gate == 2) ? Uo : Ug;
        float s = (gate < 3) ? SCL_SIG : SCL_TANH;
        g_U2[tid] = zh[it*HDIM + j] * U[j*HDIM + u] * s;
    }
}

// ---------------- 2) precompute xproj[chain][t][u][gate] ----------------
__global__ void __launch_bounds__(256) xproj_k(const float* __restrict__ x) {
    int tid = blockIdx.x * blockDim.x + threadIdx.x;     // chain-major, t fastest
    int t = tid % T_LEN;
    int chain = tid / T_LEN;
    if (chain >= NCHAIN) return;
    int it = chain / BATCH, b = chain % BATCH;
    const float* xr = x + ((size_t)t*BATCH + b)*DDIM;
    float x0 = xr[0], x1 = xr[1], x2 = xr[2];
    const float* W = g_W2 + it*DDIM*NGATE;
    float v[NGATE];
#pragma unroll
    for (int k = 0; k < NGATE; k++)
        v[k] = x0*W[k] + x1*W[NGATE + k] + x2*W[2*NGATE + k];
    float4* out = (float4*)(g_xproj + ((size_t)chain*T_LEN + t)*NGATE);
    out[0] = make_float4(v[0],  v[1],  v[2],  v[3]);
    out[1] = make_float4(v[4],  v[5],  v[6],  v[7]);
    out[2] = make_float4(v[8],  v[9],  v[10], v[11]);
    out[3] = make_float4(v[12], v[13], v[14], v[15]);
}

// ---------------- 3) serial recurrence: 4 lanes per chain, lane u owns unit u ----------
// Structure identical to the 1860us kernel; ONLY the activation implementation
// changed: tanh.approx (which ptxas expands into a long accurate sequence;
// rel_err 2e-6 proved it) is replaced by explicit single-MUFU ex2/rcp:
//   sigmoid = rcp(1 + ex2(a'))   (scale folded into weights)
//   tanh    = 2*rcp(1 + ex2(a'')) - 1
// 10 MUFU + ~7 FFMA per step instead of 5 expanded tanh (~50 instrs).
__global__ void __launch_bounds__(4, 1) lstm_k() {
    const int u     = threadIdx.x;      // 0..3 = unit
    const int chain = blockIdx.x;
    const unsigned FULL = 0xFu;

    // per-lane recurrent weights: U2[it][j][u][gate] for j=0..3 (folded)
    const float* Ub = g_U2 + (chain / BATCH)*HDIM*NGATE + u*4;
    const float4 U0 = *(const float4*)(Ub + 0*NGATE);
    const float4 U1 = *(const float4*)(Ub + 1*NGATE);
    const float4 U2v = *(const float4*)(Ub + 2*NGATE);
    const float4 U3 = *(const float4*)(Ub + 3*NGATE);

    const float4* xp  = (const float4*)(g_xproj + (size_t)chain*T_LEN*NGATE) + u;  // stride 4 float4/step
    float4*       stp = (float4*)g_scratch + (size_t)chain*4 + u;                   // stride NCHAIN*4/step

    float h = 0.f, c = 0.f;

    // 8-deep prefetch pipeline: one LDG.128 per lane per step
    float4 xbuf[8];
#pragma unroll
    for (int p = 0; p < 8; p++) xbuf[p] = xp[(size_t)p*4];

    for (int t = 0; t < T_LEN; t += 8) {
#pragma unroll
        for (int p = 0; p < 8; p++) {
            float4 xv = xbuf[p];
            int nf = t + 8 + p; nf = (nf < T_LEN) ? nf : (T_LEN - 1);
            xbuf[p] = xp[(size_t)nf*4];                  // issue-only cost, hidden in stalls

            // single shfl round: broadcast h0..h3 (lane j owns h_j)
            float h0 = __shfl_sync(FULL, h, 0, 4);
            float h1 = __shfl_sync(FULL, h, 1, 4);
            float h2 = __shfl_sync(FULL, h, 2, 4);
            float h3 = __shfl_sync(FULL, h, 3, 4);

            // four gate pre-acts for THIS unit (exp-domain scaled, trees)
            float ai = fmaf(h1, U1.x, fmaf(h0, U0.x, xv.x)) + fmaf(h3, U3.x, h2*U2v.x);
            float af = fmaf(h1, U1.y, fmaf(h0, U0.y, xv.y)) + fmaf(h3, U3.y, h2*U2v.y);
            float ao = fmaf(h1, U1.z, fmaf(h0, U0.z, xv.z)) + fmaf(h3, U3.z, h2*U2v.z);
            float ag = fmaf(h1, U1.w, fmaf(h0, U0.w, xv.w)) + fmaf(h3, U3.w, h2*U2v.w);

            // MUFU ladder, g & i first (i*g forms earliest on the c-chain)
            float eg = ex2_ap(ag);                       // 2^(-2x*log2e) = e^(-2x)
            float ei = ex2_ap(ai);
            float ef = ex2_ap(af);
            float eo = ex2_ap(ao);

            float gs = rcp_ap(1.0f + eg);                // sigma(2x_g)
            float iv = rcp_ap(1.0f + ei);
            float fv = rcp_ap(1.0f + ef);
            float ov = rcp_ap(1.0f + eo);

            float tg = fmaf(2.0f, gs, -1.0f);            // tanh(x_g)

            c = fmaf(fv, c, iv*tg);
            float cc = c * SCL_TANH;                     // -2c*log2e
            float ec = ex2_ap(cc);
            float cs = rcp_ap(1.0f + ec);
            float tc = fmaf(2.0f, cs, -1.0f);            // tanh(c)
            h = ov*tc;

            // convergent STG.128, distinct per (chain,u) addresses
            stp[(size_t)(t + p)*(NCHAIN*4)] = make_float4(ov, h, c, tc);
        }
    }
}

// ---------------- 4) deterministic mean over the 10 MC iterations ----------------
__global__ void __launch_bounds__(256) reduce_k(float* __restrict__ out) {
    int tid = blockIdx.x * blockDim.x + threadIdx.x;
    if (tid >= T_LEN*BATCH*HDIM) return;
    int u = tid & 3;
    int b = (tid >> 2) % BATCH;
    int t = tid / (BATCH*HDIM);
    const float4* base = (const float4*)g_scratch + (size_t)t*NCHAIN*4 + b*4 + u;
    float so = 0.f, sh = 0.f, scc = 0.f;
#pragma unroll
    for (int it = 0; it < NITER; it++) {
        float4 v = base[(size_t)it*BATCH*4];             // chain = it*BATCH + b
        so += v.x; sh += v.y; scc += v.z;
    }
    size_t o_idx = ((size_t)t*BATCH + b)*HDIM + u;
    const size_t TEN = (size_t)T_LEN*BATCH*HDIM;
    out[o_idx]         = 0.1f*so;
    out[TEN + o_idx]   = 0.1f*sh;
    out[2*TEN + o_idx] = 0.1f*scc;
}

// ---------------- launch ----------------
extern "C" void kernel_launch(void* const* d_in, const int* in_sizes, int n_in,
                              void* d_out, int out_size) {
    const float* input = (const float*)d_in[0];
    const float* zx    = (const float*)d_in[1];
    const float* zh    = (const float*)d_in[2];
    const float* Wi    = (const float*)d_in[3];
    const float* Ui    = (const float*)d_in[4];
    const float* Wf    = (const float*)d_in[5];
    const float* Uf    = (const float*)d_in[6];
    const float* Wo    = (const float*)d_in[7];
    const float* Uo    = (const float*)d_in[8];
    const float* Wg    = (const float*)d_in[9];
    const float* Ug    = (const float*)d_in[10];
    float* out = (float*)d_out;

    setup_k<<<1, 1024>>>(zx, zh, Wi, Ui, Wf, Uf, Wo, Uo, Wg, Ug);
    xproj_k<<<(NCHAIN*T_LEN + 255)/256, 256>>>(input);
    lstm_k<<<NCHAIN, 4>>>();
    reduce_k<<<(T_LEN*BATCH*HDIM + 255)/256, 256>>>(out);
}

// round 16
// speedup vs baseline: 1.1905x; 1.1905x over previous
#include <cuda_runtime.h>
#include <cstdint>

#define T_LEN  16384
#define BATCH  10
#define DDIM   3
#define HDIM   4
#define NITER  10
#define NCHAIN (NITER*BATCH)   // 100
#define NGATE  16

// ---------------- device scratch (static: no allocation allowed) ----------------
// layout (u-major, gate-fastest): k = u*4 + gate, gates 0=i 1=f 2=o 3=g
__device__ float g_W2[NITER*DDIM*NGATE];                // [it][d][u][gate], zx & 0.5 folded
__device__ float g_U2[NITER*HDIM*NGATE];                // [it][j][u][gate], zh & 0.5 folded
__device__ float g_xproj[(size_t)NCHAIN*T_LEN*NGATE];   // 104.9 MB  [chain][t][u][gate]
__device__ float g_scratch[(size_t)T_LEN*NCHAIN*16];    // 104.9 MB  [t][chain][u][4] = (o,h,c,tc)

// ---------------- helpers ----------------
__device__ __forceinline__ float tanh_ap(float x) {
    float y; asm("tanh.approx.f32 %0, %1;" : "=f"(y) : "f"(x)); return y;
}

// ---------------- 1) fold masks/scales into W2, U2 ----------------
// Scale 0.5 for i,f,o (sigmoid(a) = 0.5*tanh(a/2)+0.5), 1.0 for g.
__global__ void setup_k(const float* __restrict__ zx, const float* __restrict__ zh,
                        const float* __restrict__ Wi, const float* __restrict__ Ui,
                        const float* __restrict__ Wf, const float* __restrict__ Uf,
                        const float* __restrict__ Wo, const float* __restrict__ Uo,
                        const float* __restrict__ Wg, const float* __restrict__ Ug) {
    int tid = blockIdx.x * blockDim.x + threadIdx.x;
    if (tid < NITER*DDIM*NGATE) {                  // W2[it][d][u][gate]
        int k = tid % NGATE, d = (tid / NGATE) % DDIM, it = tid / (NGATE*DDIM);
        int gate = k & 3, u = k >> 2;
        const float* W = (gate == 0) ? Wi : (gate == 1) ? Wf : (gate == 2) ? Wo : Wg;
        float s = (gate < 3) ? 0.5f : 1.0f;
        g_W2[tid] = zx[it*DDIM + d] * W[d*HDIM + u] * s;
    }
    if (tid < NITER*HDIM*NGATE) {                  // U2[it][j][u][gate]
        int k = tid % NGATE, j = (tid / NGATE) % HDIM, it = tid / (NGATE*HDIM);
        int gate = k & 3, u = k >> 2;
        const float* U = (gate == 0) ? Ui : (gate == 1) ? Uf : (gate == 2) ? Uo : Ug;
        float s = (gate < 3) ? 0.5f : 1.0f;
        g_U2[tid] = zh[it*HDIM + j] * U[j*HDIM + u] * s;
    }
}

// ---------------- 2) precompute xproj[chain][t][u][gate] ----------------
__global__ void __launch_bounds__(256) xproj_k(const float* __restrict__ x) {
    int tid = blockIdx.x * blockDim.x + threadIdx.x;     // chain-major, t fastest
    int t = tid % T_LEN;
    int chain = tid / T_LEN;
    if (chain >= NCHAIN) return;
    int it = chain / BATCH, b = chain % BATCH;
    const float* xr = x + ((size_t)t*BATCH + b)*DDIM;
    float x0 = xr[0], x1 = xr[1], x2 = xr[2];
    const float* W = g_W2 + it*DDIM*NGATE;
    float v[NGATE];
#pragma unroll
    for (int k = 0; k < NGATE; k++)
        v[k] = x0*W[k] + x1*W[NGATE + k] + x2*W[2*NGATE + k];
    float4* out = (float4*)(g_xproj + ((size_t)chain*T_LEN + t)*NGATE);
    out[0] = make_float4(v[0],  v[1],  v[2],  v[3]);
    out[1] = make_float4(v[4],  v[5],  v[6],  v[7]);
    out[2] = make_float4(v[8],  v[9],  v[10], v[11]);
    out[3] = make_float4(v[12], v[13], v[14], v[15]);
}

// ---------------- 3) serial recurrence: TWO chains interleaved per warp ----------
// 4 lanes, lane u owns unit u of BOTH chains (cA = 2*blk, cB = 2*blk+1), each
// chain's state in its own registers. Chain B's independent instructions fill
// chain A's stall windows (shfl 26, tanh 16) and vice versa: per-iteration
// cost -> 2 * issue-sum instead of 2 * (issue-sum + exposed latency).
// Per-chain arithmetic is identical to the 1860us R13 kernel.
__global__ void __launch_bounds__(4, 1) lstm_k() {
    const int u  = threadIdx.x;          // 0..3 = unit
    const int cA = 2*blockIdx.x;
    const int cB = cA + 1;
    const unsigned FULL = 0xFu;

    // per-lane recurrent weights for both chains (folded)
    const float* UbA = g_U2 + (cA / BATCH)*HDIM*NGATE + u*4;
    const float4 A0 = *(const float4*)(UbA + 0*NGATE);
    const float4 A1 = *(const float4*)(UbA + 1*NGATE);
    const float4 A2 = *(const float4*)(UbA + 2*NGATE);
    const float4 A3 = *(const float4*)(UbA + 3*NGATE);
    const float* UbB = g_U2 + (cB / BATCH)*HDIM*NGATE + u*4;
    const float4 B0 = *(const float4*)(UbB + 0*NGATE);
    const float4 B1 = *(const float4*)(UbB + 1*NGATE);
    const float4 B2 = *(const float4*)(UbB + 2*NGATE);
    const float4 B3 = *(const float4*)(UbB + 3*NGATE);

    const float4* xpA = (const float4*)(g_xproj + (size_t)cA*T_LEN*NGATE) + u;
    const float4* xpB = (const float4*)(g_xproj + (size_t)cB*T_LEN*NGATE) + u;
    float4* stA = (float4*)g_scratch + (size_t)cA*4 + u;     // stride NCHAIN*4/step
    float4* stB = (float4*)g_scratch + (size_t)cB*4 + u;

    float hA = 0.f, cAs = 0.f;
    float hB = 0.f, cBs = 0.f;

    // 8-deep prefetch pipelines (one LDG.128 per lane per chain per step)
    float4 xbA[8], xbB[8];
#pragma unroll
    for (int p = 0; p < 8; p++) { xbA[p] = xpA[(size_t)p*4]; xbB[p] = xpB[(size_t)p*4]; }

    for (int t = 0; t < T_LEN; t += 8) {
#pragma unroll
        for (int p = 0; p < 8; p++) {
            int nf = t + 8 + p; nf = (nf < T_LEN) ? nf : (T_LEN - 1);

            // ---- shfl rounds for both chains (independent -> overlap) ----
            float a0 = __shfl_sync(FULL, hA, 0, 4);
            float b0 = __shfl_sync(FULL, hB, 0, 4);
            float a1 = __shfl_sync(FULL, hA, 1, 4);
            float b1 = __shfl_sync(FULL, hB, 1, 4);
            float a2 = __shfl_sync(FULL, hA, 2, 4);
            float b2 = __shfl_sync(FULL, hB, 2, 4);
            float a3 = __shfl_sync(FULL, hA, 3, 4);
            float b3 = __shfl_sync(FULL, hB, 3, 4);

            float4 xvA = xbA[p];  xbA[p] = xpA[(size_t)nf*4];
            float4 xvB = xbB[p];  xbB[p] = xpB[(size_t)nf*4];

            // ---- gate pre-acts, chain A then chain B (ptxas interleaves) ----
            float aiA = fmaf(a1, A1.x, fmaf(a0, A0.x, xvA.x)) + fmaf(a3, A3.x, a2*A2.x);
            float aiB = fmaf(b1, B1.x, fmaf(b0, B0.x, xvB.x)) + fmaf(b3, B3.x, b2*B2.x);
            float afA = fmaf(a1, A1.y, fmaf(a0, A0.y, xvA.y)) + fmaf(a3, A3.y, a2*A2.y);
            float afB = fmaf(b1, B1.y, fmaf(b0, B0.y, xvB.y)) + fmaf(b3, B3.y, b2*B2.y);
            float aoA = fmaf(a1, A1.z, fmaf(a0, A0.z, xvA.z)) + fmaf(a3, A3.z, a2*A2.z);
            float aoB = fmaf(b1, B1.z, fmaf(b0, B0.z, xvB.z)) + fmaf(b3, B3.z, b2*B2.z);
            float agA = fmaf(a1, A1.w, fmaf(a0, A0.w, xvA.w)) + fmaf(a3, A3.w, a2*A2.w);
            float agB = fmaf(b1, B1.w, fmaf(b0, B0.w, xvB.w)) + fmaf(b3, B3.w, b2*B2.w);

            // ---- MUFU ladders (g,i first), A/B interleaved ----
            float tgA = tanh_ap(agA);
            float tgB = tanh_ap(agB);
            float tiA = tanh_ap(aiA);
            float tiB = tanh_ap(aiB);
            float tfA = tanh_ap(afA);
            float tfB = tanh_ap(afB);
            float toA = tanh_ap(aoA);
            float toB = tanh_ap(aoB);

            // sigmoid(x) = 0.5*tanh(x/2)+0.5 (the /2 is folded into W2/U2)
            float ivA = fmaf(tiA, 0.5f, 0.5f), ivB = fmaf(tiB, 0.5f, 0.5f);
            float fvA = fmaf(tfA, 0.5f, 0.5f), fvB = fmaf(tfB, 0.5f, 0.5f);
            float ovA = fmaf(toA, 0.5f, 0.5f), ovB = fmaf(toB, 0.5f, 0.5f);

            cAs = fmaf(fvA, cAs, ivA*tgA);
            cBs = fmaf(fvB, cBs, ivB*tgB);
            float tcA = tanh_ap(cAs);
            float tcB = tanh_ap(cBs);
            hA = ovA*tcA;
            hB = ovB*tcB;

            // convergent STG.128 per chain, distinct addresses
            stA[(size_t)(t + p)*(NCHAIN*4)] = make_float4(ovA, hA, cAs, tcA);
            stB[(size_t)(t + p)*(NCHAIN*4)] = make_float4(ovB, hB, cBs, tcB);
        }
    }
}

// ---------------- 4) deterministic mean over the 10 MC iterations ----------------
__global__ void __launch_bounds__(256) reduce_k(float* __restrict__ out) {
    int tid = blockIdx.x * blockDim.x + threadIdx.x;
    if (tid >= T_LEN*BATCH*HDIM) return;
    int u = tid & 3;
    int b = (tid >> 2) % BATCH;
    int t = tid / (BATCH*HDIM);
    const float4* base = (const float4*)g_scratch + (size_t)t*NCHAIN*4 + b*4 + u;
    float so = 0.f, sh = 0.f, scc = 0.f;
#pragma unroll
    for (int it = 0; it < NITER; it++) {
        float4 v = base[(size_t)it*BATCH*4];             // chain = it*BATCH + b
        so += v.x; sh += v.y; scc += v.z;
    }
    size_t o_idx = ((size_t)t*BATCH + b)*HDIM + u;
    const size_t TEN = (size_t)T_LEN*BATCH*HDIM;
    out[o_idx]         = 0.1f*so;
    out[TEN + o_idx]   = 0.1f*sh;
    out[2*TEN + o_idx] = 0.1f*scc;
}

// ---------------- launch ----------------
extern "C" void kernel_launch(void* const* d_in, const int* in_sizes, int n_in,
                              void* d_out, int out_size) {
    const float* input = (const float*)d_in[0];
    const float* zx    = (const float*)d_in[1];
    const float* zh    = (const float*)d_in[2];
    const float* Wi    = (const float*)d_in[3];
    const float* Ui    = (const float*)d_in[4];
    const float* Wf    = (const float*)d_in[5];
    const float* Uf    = (const float*)d_in[6];
    const float* Wo    = (const float*)d_in[7];
    const float* Uo    = (const float*)d_in[8];
    const float* Wg    = (const float*)d_in[9];
    const float* Ug    = (const float*)d_in[10];
    float* out = (float*)d_out;

    setup_k<<<1, 1024>>>(zx, zh, Wi, Ui, Wf, Uf, Wo, Uo, Wg, Ug);
    xproj_k<<<(NCHAIN*T_LEN + 255)/256, 256>>>(input);
    lstm_k<<<NCHAIN/2, 4>>>();
    reduce_k<<<(T_LEN*BATCH*HDIM + 255)/256, 256>>>(out);
}

// round 17
// speedup vs baseline: 1.4644x; 1.2301x over previous
#include <cuda_runtime.h>
#include <cstdint>

#define T_LEN  16384
#define BATCH  10
#define DDIM   3
#define HDIM   4
#define NITER  10
#define NCHAIN (NITER*BATCH)   // 100
#define NGATE  16
#define PFD    8               // prefetch depth (steps)

// ---------------- device scratch (static: no allocation allowed) ----------------
// layout (u-major, gate-fastest): k = u*4 + gate, gates 0=i 1=f 2=o 3=g
__device__ float g_W2[NITER*DDIM*NGATE];                // [it][d][u][gate], zx & 0.5 folded
__device__ float g_U2[NITER*HDIM*NGATE];                // [it][j][u][gate], zh & 0.5 folded
__device__ float g_xproj[(size_t)NCHAIN*T_LEN*NGATE + PFD*NGATE]; // padded: clamp-free prefetch
__device__ float g_scratch[(size_t)T_LEN*NCHAIN*16];    // [t][chain][u][4] = (o,h,c,tc)

// ---------------- helpers ----------------
__device__ __forceinline__ float tanh_ap(float x) {
    float y; asm("tanh.approx.f32 %0, %1;" : "=f"(y) : "f"(x)); return y;
}

// ---------------- 1) fold masks/scales into W2, U2 ----------------
// Scale 0.5 for i,f,o (sigmoid(a) = 0.5*tanh(a/2)+0.5), 1.0 for g.
__global__ void setup_k(const float* __restrict__ zx, const float* __restrict__ zh,
                        const float* __restrict__ Wi, const float* __restrict__ Ui,
                        const float* __restrict__ Wf, const float* __restrict__ Uf,
                        const float* __restrict__ Wo, const float* __restrict__ Uo,
                        const float* __restrict__ Wg, const float* __restrict__ Ug) {
    int tid = blockIdx.x * blockDim.x + threadIdx.x;
    if (tid < NITER*DDIM*NGATE) {                  // W2[it][d][u][gate]
        int k = tid % NGATE, d = (tid / NGATE) % DDIM, it = tid / (NGATE*DDIM);
        int gate = k & 3, u = k >> 2;
        const float* W = (gate == 0) ? Wi : (gate == 1) ? Wf : (gate == 2) ? Wo : Wg;
        float s = (gate < 3) ? 0.5f : 1.0f;
        g_W2[tid] = zx[it*DDIM + d] * W[d*HDIM + u] * s;
    }
    if (tid < NITER*HDIM*NGATE) {                  // U2[it][j][u][gate]
        int k = tid % NGATE, j = (tid / NGATE) % HDIM, it = tid / (NGATE*HDIM);
        int gate = k & 3, u = k >> 2;
        const float* U = (gate == 0) ? Ui : (gate == 1) ? Uf : (gate == 2) ? Uo : Ug;
        float s = (gate < 3) ? 0.5f : 1.0f;
        g_U2[tid] = zh[it*HDIM + j] * U[j*HDIM + u] * s;
    }
}

// ---------------- 2) precompute xproj[chain][t][u][gate] ----------------
__global__ void __launch_bounds__(256) xproj_k(const float* __restrict__ x) {
    int tid = blockIdx.x * blockDim.x + threadIdx.x;     // chain-major, t fastest
    int t = tid % T_LEN;
    int chain = tid / T_LEN;
    if (chain >= NCHAIN) return;
    int it = chain / BATCH, b = chain % BATCH;
    const float* xr = x + ((size_t)t*BATCH + b)*DDIM;
    float x0 = xr[0], x1 = xr[1], x2 = xr[2];
    const float* W = g_W2 + it*DDIM*NGATE;
    float v[NGATE];
#pragma unroll
    for (int k = 0; k < NGATE; k++)
        v[k] = x0*W[k] + x1*W[NGATE + k] + x2*W[2*NGATE + k];
    float4* out = (float4*)(g_xproj + ((size_t)chain*T_LEN + t)*NGATE);
    out[0] = make_float4(v[0],  v[1],  v[2],  v[3]);
    out[1] = make_float4(v[4],  v[5],  v[6],  v[7]);
    out[2] = make_float4(v[8],  v[9],  v[10], v[11]);
    out[3] = make_float4(v[12], v[13], v[14], v[15]);
}

// ---------------- 3) serial recurrence: 4 lanes per chain, lane u owns unit u ----------
// Same dataflow/arithmetic as the 1860us R13 kernel. Two changes:
//  (a) h-exchange via warp-synchronous VOLATILE shared memory instead of 4
//      shfls: lane u does one st.volatile.shared.f32 of h_u; all lanes read
//      h0..h3 back with a single ld.volatile.shared.v4.f32 (LDS.128
//      broadcast). Fully convergent single warp; LSU processes same-warp smem
//      ops in program order; volatile pins compile-time ordering.
//  (b) xproj padded by PFD steps -> clamp-free prefetch (no SEL/IMNMX).
__global__ void __launch_bounds__(4, 1) lstm_k() {
    __shared__ float sh[4];
    const int u     = threadIdx.x;      // 0..3 = unit
    const int chain = blockIdx.x;

    unsigned shb  = (unsigned)__cvta_generic_to_shared(sh);
    unsigned shu  = shb + 4u*u;         // this lane's h slot

    // per-lane recurrent weights: U2[it][j][u][gate] for j=0..3 (folded)
    const float* Ub = g_U2 + (chain / BATCH)*HDIM*NGATE + u*4;
    const float4 U0 = *(const float4*)(Ub + 0*NGATE);
    const float4 U1 = *(const float4*)(Ub + 1*NGATE);
    const float4 U2v = *(const float4*)(Ub + 2*NGATE);
    const float4 U3 = *(const float4*)(Ub + 3*NGATE);

    const float4* xp  = (const float4*)(g_xproj + (size_t)chain*T_LEN*NGATE) + u;  // stride 4 float4/step
    float4*       stp = (float4*)g_scratch + (size_t)chain*4 + u;                   // stride NCHAIN*4/step

    float h = 0.f, c = 0.f;

    // 8-deep prefetch pipeline: one LDG.128 per lane per step (padded, clamp-free)
    float4 xbuf[PFD];
#pragma unroll
    for (int p = 0; p < PFD; p++) xbuf[p] = xp[(size_t)p*4];

    for (int t = 0; t < T_LEN; t += PFD) {
#pragma unroll
        for (int p = 0; p < PFD; p++) {
            float4 xv = xbuf[p];
            xbuf[p] = xp[(size_t)(t + PFD + p)*4];       // padded: no clamp

            // ---- h exchange through volatile smem (replaces 4 shfls) ----
            asm volatile("st.volatile.shared.f32 [%0], %1;" :: "r"(shu), "f"(h));
            float h0, h1, h2, h3;
            asm volatile("ld.volatile.shared.v4.f32 {%0,%1,%2,%3}, [%4];"
                         : "=f"(h0), "=f"(h1), "=f"(h2), "=f"(h3) : "r"(shb));

            // four gate pre-acts for THIS unit (balanced trees)
            float ai = fmaf(h1, U1.x, fmaf(h0, U0.x, xv.x)) + fmaf(h3, U3.x, h2*U2v.x);
            float af = fmaf(h1, U1.y, fmaf(h0, U0.y, xv.y)) + fmaf(h3, U3.y, h2*U2v.y);
            float ao = fmaf(h1, U1.z, fmaf(h0, U0.z, xv.z)) + fmaf(h3, U3.z, h2*U2v.z);
            float ag = fmaf(h1, U1.w, fmaf(h0, U0.w, xv.w)) + fmaf(h3, U3.w, h2*U2v.w);

            // MUFU order: g,i first (i*g forms earliest), then f, then o
            float tg_ = tanh_ap(ag);
            float ti_ = tanh_ap(ai);
            float tf_ = tanh_ap(af);
            float to_ = tanh_ap(ao);

            // sigmoid(x) = 0.5*tanh(x/2)+0.5 (the /2 is folded into W2/U2)
            float iv = fmaf(ti_, 0.5f, 0.5f);
            float fv = fmaf(tf_, 0.5f, 0.5f);
            float ov = fmaf(to_, 0.5f, 0.5f);

            c = fmaf(fv, c, iv*tg_);
            float tc = tanh_ap(c);
            h = ov*tc;

            // convergent STG.128, distinct per (chain,u) addresses
            stp[(size_t)(t + p)*(NCHAIN*4)] = make_float4(ov, h, c, tc);
        }
    }
}

// ---------------- 4) deterministic mean over the 10 MC iterations ----------------
__global__ void __launch_bounds__(256) reduce_k(float* __restrict__ out) {
    int tid = blockIdx.x * blockDim.x + threadIdx.x;
    if (tid >= T_LEN*BATCH*HDIM) return;
    int u = tid & 3;
    int b = (tid >> 2) % BATCH;
    int t = tid / (BATCH*HDIM);
    const float4* base = (const float4*)g_scratch + (size_t)t*NCHAIN*4 + b*4 + u;
    float so = 0.f, sh = 0.f, scc = 0.f;
#pragma unroll
    for (int it = 0; it < NITER; it++) {
        float4 v = base[(size_t)it*BATCH*4];             // chain = it*BATCH + b
        so += v.x; sh += v.y; scc += v.z;
    }
    size_t o_idx = ((size_t)t*BATCH + b)*HDIM + u;
    const size_t TEN = (size_t)T_LEN*BATCH*HDIM;
    out[o_idx]         = 0.1f*so;
    out[TEN + o_idx]   = 0.1f*sh;
    out[2*TEN + o_idx] = 0.1f*scc;
}

// ---------------- launch ----------------
extern "C" void kernel_launch(void* const* d_in, const int* in_sizes, int n_in,
                              void* d_out, int out_size) {
    const float* input = (const float*)d_in[0];
    const float* zx    = (const float*)d_in[1];
    const float* zh    = (const float*)d_in[2];
    const float* Wi    = (const float*)d_in[3];
    const float* Ui    = (const float*)d_in[4];
    const float* Wf    = (const float*)d_in[5];
    const float* Uf    = (const float*)d_in[6];
    const float* Wo    = (const float*)d_in[7];
    const float* Uo    = (const float*)d_in[8];
    const float* Wg    = (const float*)d_in[9];
    const float* Ug    = (const float*)d_in[10];
    float* out = (float*)d_out;

    setup_k<<<1, 1024>>>(zx, zh, Wi, Ui, Wf, Uf, Wo, Uo, Wg, Ug);
    xproj_k<<<(NCHAIN*T_LEN + 255)/256, 256>>>(input);
    lstm_k<<<NCHAIN, 4>>>();
    reduce_k<<<(T_LEN*BATCH*HDIM + 255)/256, 256>>>(out);
}